// round 9
// baseline (speedup 1.0000x reference)
#include <cuda_runtime.h>
#include <cstdint>

// IFS trajectory — 4 blocks/SM, depth-2 cp.async pipeline, f32x2 math.
// inputs: d_in[0] = coef (BATCH, 12) f32, d_in[1] = h (ITERS, BATCH) f32
// output: (BATCH, ITERS+1, 2) f32
//
// Column tiling, TILE=8: tile t owns output cols [8t, 8t+8); col c>0 consumes
// h[c-1], col 0 is the initial point. h ring: 4 buffers, prefetch 2 ahead via
// cp.async.cg. One __syncthreads per tile (also orders ring reuse: a thread
// issuing prefetch(t+2) passed barrier #t, so every thread finished reading
// buffer (t+2)&3 at iteration t-2). Staging columns are per-warp -> __syncwarp.
// Flush: quarter-warp writes one row's 8 float2 = 64B contiguous.
//
// R8 bug fixed here: prefetch must cover 512 x 16B chunks per tile
// (8 rows x 256 floats), i.e. 2 chunks per thread — R8 issued only 128.

#define BLOCK 256
#define TILE  8
#define NBUF  4

typedef unsigned long long ull;

__device__ __forceinline__ void cp_async16(uint32_t saddr, const void* gptr) {
    asm volatile("cp.async.cg.shared.global [%0], [%1], 16;\n"
                 :: "r"(saddr), "l"(gptr));
}
__device__ __forceinline__ void cp_commit() {
    asm volatile("cp.async.commit_group;\n");
}
template <int N>
__device__ __forceinline__ void cp_wait() {
    asm volatile("cp.async.wait_group %0;\n" :: "n"(N));
}

__device__ __forceinline__ ull pk2(float lo, float hi) {
    ull r; asm("mov.b64 %0, {%1, %2};" : "=l"(r) : "f"(lo), "f"(hi)); return r;
}
__device__ __forceinline__ void unpk2(ull v, float& lo, float& hi) {
    asm("mov.b64 {%0, %1}, %2;" : "=f"(lo), "=f"(hi) : "l"(v));
}
__device__ __forceinline__ ull fma2(ull a, ull b, ull c) {
    ull d; asm("fma.rn.f32x2 %0, %1, %2, %3;" : "=l"(d) : "l"(a), "l"(b), "l"(c));
    return d;
}
__device__ __forceinline__ ull selgt(float ht, float p, ull a, ull b) {
    ull r;
    asm("{\n\t.reg .pred q;\n\t"
        "setp.gt.f32 q, %1, %2;\n\t"
        "selp.b64 %0, %3, %4, q;\n\t}"
        : "=l"(r) : "f"(ht), "f"(p), "l"(a), "l"(b));
    return r;
}

__device__ __forceinline__ void ifs_step(
    ull& xy, float& xv, float& yv, float ht, float p,
    ull cAad, ull cAbc, ull cAef, ull cBad, ull cBbc, ull cBef)
{
    ull s  = pk2(yv, xv);
    ull rA = fma2(cAad, xy, fma2(cAbc, s, cAef));
    ull rB = fma2(cBad, xy, fma2(cBbc, s, cBef));
    xy = selgt(ht, p, rB, rA);
    unpk2(xy, xv, yv);
}

template <int BATCH_C, int ITERS_C>
__global__ __launch_bounds__(BLOCK, 4) void ifs_spec(
    const float* __restrict__ coef,
    const float* __restrict__ h,
    float2* __restrict__ out)
{
    constexpr int STRIDE = ITERS_C + 1;             // 101
    constexpr int NTILE  = STRIDE / TILE;           // 12 (cols 0..95)
    constexpr int TREM   = STRIDE - NTILE * TILE;   // 5  (cols 96..100)

    __shared__ __align__(16) float sh[NBUF][TILE][BLOCK];  // 32 KB
    __shared__ float2 so[TILE][BLOCK + 2];                  // 16.5 KB

    const int tid  = threadIdx.x;
    const int block_b0 = blockIdx.x * BLOCK;

    // ---------------- partial last block: simple per-thread path -----------
    if (block_b0 + BLOCK > BATCH_C) {
        const int b = block_b0 + tid;
        if (b >= BATCH_C) return;
        const float4* c4 = reinterpret_cast<const float4*>(coef + (size_t)b * 12);
        float4 ca = c4[0], cb = c4[1], cc = c4[2];
        float A0=ca.x, A1=ca.y, A2=ca.z, A3=ca.w, A4=cb.x, A5=cb.y;
        float B0=cb.z, B1=cb.w, B2=cc.x, B3=cc.y, B4=cc.z, B5=cc.w;
        float j0 = fabsf(A0*A3 - A1*A2);
        float j1 = fabsf(B0*B3 - B1*B2);
        float p = j0 / (j0 + j1);
        float x = 0.05f, y = 0.05f;
        float2* o = out + (size_t)b * STRIDE;
        o[0] = make_float2(x, y);
        #pragma unroll 4
        for (int t = 0; t < ITERS_C; ++t) {
            float ht = __ldg(h + (size_t)t * BATCH_C + b);
            bool m = ht > p;
            float xn = fmaf(m?B0:A0, x, fmaf(m?B1:A1, y, m?B4:A4));
            float yn = fmaf(m?B2:A2, x, fmaf(m?B3:A3, y, m?B5:A5));
            x = xn; y = yn;
            o[t + 1] = make_float2(x, y);
        }
        return;
    }

    // ---------------- full blocks: checkless fast path ----------------------
    const int warp = tid >> 5;
    const int lane = tid & 31;

    ull cAad, cAbc, cAef, cBad, cBbc, cBef;
    float p;
    {
        const int b = block_b0 + tid;
        const float4* c4 = reinterpret_cast<const float4*>(coef + (size_t)b * 12);
        float4 ca = c4[0], cb = c4[1], cc = c4[2];
        float A0=ca.x, A1=ca.y, A2=ca.z, A3=ca.w, A4=cb.x, A5=cb.y;
        float B0=cb.z, B1=cb.w, B2=cc.x, B3=cc.y, B4=cc.z, B5=cc.w;
        float j0 = fabsf(A0*A3 - A1*A2);
        float j1 = fabsf(B0*B3 - B1*B2);
        p = j0 / (j0 + j1);
        cAad = pk2(A0, A3); cAbc = pk2(A1, A2); cAef = pk2(A4, A5);
        cBad = pk2(B0, B3); cBbc = pk2(B1, B2); cBef = pk2(B4, B5);
    }
    ull  xy = pk2(0.05f, 0.05f);
    float xv = 0.05f, yv = 0.05f;

    // ---- prefetch: tile t loads h rows (8t-1+row), row=0..7.
    //      One tile = 8 rows x 256 floats = 512 x 16B chunks = 2 per thread.
    const uint32_t sh_base = (uint32_t)__cvta_generic_to_shared(&sh[0][0][0]);
    auto prefetch = [&](int tile) {
        if (tile < NTILE) {
            const int buf = tile & (NBUF - 1);
            #pragma unroll
            for (int i = 0; i < 2; ++i) {
                const int flat = tid + i * BLOCK;     // 0..511
                const int row  = flat >> 6;           // 0..7 (64 chunks/row)
                const int c4   = (flat & 63) << 2;    // float col 0..252
                const int rg   = tile * TILE - 1 + row;
                if (rg >= 0)                           // only tile 0, row 0 skips
                    cp_async16(sh_base +
                               (uint32_t)(((buf * TILE + row) * BLOCK + c4) << 2),
                               h + (size_t)rg * BATCH_C + block_b0 + c4);
            }
        }
        cp_commit();
    };

    prefetch(0);
    prefetch(1);

    const int q   = lane >> 3;          // quarter-warp -> column group
    const int ttf = lane & 7;           // time index for flush
    const int wcol = warp * 32 + q;     // this lane's staging column base

    for (int tile = 0; tile < NTILE; ++tile) {
        prefetch(tile + 2);
        cp_wait<2>();
        __syncthreads();                 // h tile ready; also orders ring reuse

        const int buf = tile & (NBUF - 1);

        // ---- stage 8 output columns ----
        if (tile == 0) {
            *reinterpret_cast<ull*>(&so[0][tid]) = pk2(0.05f, 0.05f);
            #pragma unroll
            for (int j = 1; j < TILE; ++j) {
                ifs_step(xy, xv, yv, sh[buf][j][tid], p,
                         cAad, cAbc, cAef, cBad, cBbc, cBef);
                *reinterpret_cast<ull*>(&so[j][tid]) = xy;
            }
        } else {
            #pragma unroll
            for (int j = 0; j < TILE; ++j) {
                ifs_step(xy, xv, yv, sh[buf][j][tid], p,
                         cAad, cAbc, cAef, cBad, cBbc, cBef);
                *reinterpret_cast<ull*>(&so[j][tid]) = xy;
            }
        }
        __syncwarp();

        // ---- flush: quarter-warp writes one row's 8 float2 = 64B ----
        {
            float2* obase = out + (size_t)(block_b0 + wcol) * STRIDE
                          + tile * TILE + ttf;
            const float2* srow = &so[ttf][wcol];
            #pragma unroll
            for (int k = 0; k < 8; ++k)
                obase[(size_t)(4 * k) * STRIDE] = srow[4 * k];
        }
        __syncwarp();
    }

    // ---- tail: cols 96..100 consume h rows 95..99 ----
    {
        #pragma unroll
        for (int j = 0; j < TREM; ++j) {
            float ht = __ldg(h + (size_t)(NTILE * TILE - 1 + j) * BATCH_C
                             + block_b0 + tid);
            ifs_step(xy, xv, yv, ht, p,
                     cAad, cAbc, cAef, cBad, cBbc, cBef);
            *reinterpret_cast<ull*>(&so[j][tid]) = xy;
        }
        __syncwarp();
        if (ttf < TREM) {
            float2* obase = out + (size_t)(block_b0 + wcol) * STRIDE
                          + NTILE * TILE + ttf;
            const float2* srow = &so[ttf][wcol];
            #pragma unroll
            for (int k = 0; k < 8; ++k)
                obase[(size_t)(4 * k) * STRIDE] = srow[4 * k];
        }
    }
}

// ---- generic fallback (any shape) ----
__global__ void ifs_generic(const float* __restrict__ coef,
                            const float* __restrict__ h,
                            float2* __restrict__ out,
                            int batch, int iters)
{
    int b = blockIdx.x * blockDim.x + threadIdx.x;
    if (b >= batch) return;
    const float4* c4 = reinterpret_cast<const float4*>(coef + (size_t)b * 12);
    float4 ca = c4[0], cb = c4[1], cc = c4[2];
    float A0=ca.x, A1=ca.y, A2=ca.z, A3=ca.w, A4=cb.x, A5=cb.y;
    float B0=cb.z, B1=cb.w, B2=cc.x, B3=cc.y, B4=cc.z, B5=cc.w;
    float j0 = fabsf(A0*A3 - A1*A2);
    float j1 = fabsf(B0*B3 - B1*B2);
    float p = j0 / (j0 + j1);
    float x = 0.05f, y = 0.05f;
    float2* o = out + (size_t)b * (iters + 1);
    o[0] = make_float2(x, y);
    for (int t = 0; t < iters; ++t) {
        float ht = __ldg(h + (size_t)t * batch + b);
        bool m = ht > p;
        float xn = fmaf(m?B0:A0, x, fmaf(m?B1:A1, y, m?B4:A4));
        float yn = fmaf(m?B2:A2, x, fmaf(m?B3:A3, y, m?B5:A5));
        x = xn; y = yn;
        o[t + 1] = make_float2(x, y);
    }
}

extern "C" void kernel_launch(void* const* d_in, const int* in_sizes, int n_in,
                              void* d_out, int out_size) {
    const float* coef = (const float*)d_in[0];
    const float* h    = (const float*)d_in[1];
    float2* out       = (float2*)d_out;

    int batch = in_sizes[0] / 12;
    int iters = in_sizes[1] / batch;

    if (batch == 200000 && iters == 100) {
        int blocks = (batch + BLOCK - 1) / BLOCK;
        ifs_spec<200000, 100><<<blocks, BLOCK>>>(coef, h, out);
    } else {
        int blocks = (batch + 255) / 256;
        ifs_generic<<<blocks, 256>>>(coef, h, out, batch, iters);
    }
}

// round 10
// speedup vs baseline: 1.1727x; 1.1727x over previous
#include <cuda_runtime.h>
#include <cstdint>

// IFS trajectory — BLOCK=128, 6 blocks/SM, TILE=16, depth-1 cp.async, scalar math.
// inputs: d_in[0] = coef (BATCH, 12) f32, d_in[1] = h (ITERS, BATCH) f32
// output: (BATCH, ITERS+1, 2) f32
//
// Column tiling: tile t owns output cols [16t,16t+16); col c>0 consumes h[c-1],
// col 0 is the initial point (folded into tile 0). Tile t prefetches h rows
// 16t-1+row, row=0..15 (row 0 of tile 0 skipped).
// Small barrier groups (4 warps) + 6 independent per-SM pipelines decorrelate
// the memory phases that serialized the 8-warp variants.

#define BLOCK 128
#define TILE  16
#define NBUF  2
#define SOROW 133   // staging row length in float2; odd -> flush LDS conflict <= 2-way

typedef unsigned long long ull;

__device__ __forceinline__ void cp_async16(uint32_t saddr, const void* gptr) {
    asm volatile("cp.async.cg.shared.global [%0], [%1], 16;\n"
                 :: "r"(saddr), "l"(gptr));
}
__device__ __forceinline__ void cp_commit() {
    asm volatile("cp.async.commit_group;\n");
}
template <int N>
__device__ __forceinline__ void cp_wait() {
    asm volatile("cp.async.wait_group %0;\n" :: "n"(N));
}

template <int BATCH_C, int ITERS_C>
__global__ __launch_bounds__(BLOCK, 6) void ifs_spec(
    const float* __restrict__ coef,
    const float* __restrict__ h,
    float2* __restrict__ out)
{
    constexpr int STRIDE = ITERS_C + 1;             // 101
    constexpr int NTILE  = STRIDE / TILE;           // 6  (cols 0..95)
    constexpr int TREM   = STRIDE - NTILE * TILE;   // 5  (cols 96..100)

    __shared__ __align__(16) float sh[NBUF][TILE][BLOCK];  // 16 KB
    __shared__ float2 so[TILE][SOROW];                      // ~17 KB

    const int tid  = threadIdx.x;
    const int block_b0 = blockIdx.x * BLOCK;

    // ---------------- partial last block: simple per-thread path -----------
    if (block_b0 + BLOCK > BATCH_C) {
        const int b = block_b0 + tid;
        if (b >= BATCH_C) return;
        const float4* c4 = reinterpret_cast<const float4*>(coef + (size_t)b * 12);
        float4 ca = c4[0], cb = c4[1], cc = c4[2];
        float A0=ca.x, A1=ca.y, A2=ca.z, A3=ca.w, A4=cb.x, A5=cb.y;
        float B0=cb.z, B1=cb.w, B2=cc.x, B3=cc.y, B4=cc.z, B5=cc.w;
        float j0 = fabsf(A0*A3 - A1*A2);
        float j1 = fabsf(B0*B3 - B1*B2);
        float p = j0 / (j0 + j1);
        float x = 0.05f, y = 0.05f;
        float2* o = out + (size_t)b * STRIDE;
        o[0] = make_float2(x, y);
        #pragma unroll 4
        for (int t = 0; t < ITERS_C; ++t) {
            float ht = __ldg(h + (size_t)t * BATCH_C + b);
            bool m = ht > p;
            float xn = fmaf(m?B0:A0, x, fmaf(m?B1:A1, y, m?B4:A4));
            float yn = fmaf(m?B2:A2, x, fmaf(m?B3:A3, y, m?B5:A5));
            x = xn; y = yn;
            o[t + 1] = make_float2(x, y);
        }
        return;
    }

    // ---------------- full blocks: checkless fast path ----------------------
    const int warp = tid >> 5;
    const int lane = tid & 31;

    float A0,A1,A2,A3,A4,A5,B0,B1,B2,B3,B4,B5,p;
    {
        const int b = block_b0 + tid;
        const float4* c4 = reinterpret_cast<const float4*>(coef + (size_t)b * 12);
        float4 ca = c4[0], cb = c4[1], cc = c4[2];
        A0=ca.x; A1=ca.y; A2=ca.z; A3=ca.w; A4=cb.x; A5=cb.y;
        B0=cb.z; B1=cb.w; B2=cc.x; B3=cc.y; B4=cc.z; B5=cc.w;
        float j0 = fabsf(A0*A3 - A1*A2);
        float j1 = fabsf(B0*B3 - B1*B2);
        p = j0 / (j0 + j1);
    }
    float x = 0.05f, y = 0.05f;

    // ---- prefetch: tile = 16 rows x 128 floats = 512 x 16B chunks, 4/thread
    const uint32_t sh_base = (uint32_t)__cvta_generic_to_shared(&sh[0][0][0]);
    auto prefetch = [&](int tile) {
        if (tile < NTILE) {
            const int buf = tile & (NBUF - 1);
            #pragma unroll
            for (int i = 0; i < 4; ++i) {
                const int flat = tid + i * BLOCK;     // 0..511
                const int row  = flat >> 5;           // 0..15 (32 chunks/row)
                const int c4   = (flat & 31) << 2;    // float col 0..124
                const int rg   = tile * TILE - 1 + row;
                if (rg >= 0)                           // only tile 0, row 0 skips
                    cp_async16(sh_base +
                               (uint32_t)(((buf * TILE + row) * BLOCK + c4) << 2),
                               h + (size_t)rg * BATCH_C + block_b0 + c4);
            }
        }
        cp_commit();
    };

    prefetch(0);

    const int rh  = lane >> 4;          // half-warp -> row parity
    const int ttf = lane & 15;          // time index for flush
    const int wcol = warp * 32 + rh;    // this lane's staging column base

    for (int tile = 0; tile < NTILE; ++tile) {
        prefetch(tile + 1);
        cp_wait<1>();
        __syncthreads();                 // h tile `tile` ready

        const int buf = tile & (NBUF - 1);

        // ---- stage 16 output columns ----
        if (tile == 0) {
            so[0][tid] = make_float2(0.05f, 0.05f);
            #pragma unroll
            for (int j = 1; j < TILE; ++j) {
                float ht = sh[buf][j][tid];
                float xA = fmaf(A0, x, fmaf(A1, y, A4));
                float yA = fmaf(A2, x, fmaf(A3, y, A5));
                float xB = fmaf(B0, x, fmaf(B1, y, B4));
                float yB = fmaf(B2, x, fmaf(B3, y, B5));
                bool m = ht > p;
                x = m ? xB : xA;
                y = m ? yB : yA;
                so[j][tid] = make_float2(x, y);
            }
        } else {
            #pragma unroll
            for (int j = 0; j < TILE; ++j) {
                float ht = sh[buf][j][tid];
                float xA = fmaf(A0, x, fmaf(A1, y, A4));
                float yA = fmaf(A2, x, fmaf(A3, y, A5));
                float xB = fmaf(B0, x, fmaf(B1, y, B4));
                float yB = fmaf(B2, x, fmaf(B3, y, B5));
                bool m = ht > p;
                x = m ? xB : xA;
                y = m ? yB : yA;
                so[j][tid] = make_float2(x, y);
            }
        }
        __syncwarp();

        // ---- flush: half-warp writes one row's 16 float2 = 128B line ----
        {
            float2* obase = out + (size_t)(block_b0 + wcol) * STRIDE
                          + tile * TILE + ttf;
            #pragma unroll
            for (int k = 0; k < 16; ++k)
                obase[(size_t)(2 * k) * STRIDE] = so[ttf][wcol + 2 * k];
        }
        __syncthreads();                 // all reads of sh[buf]/so done
    }

    // ---- tail: cols 96..100 consume h rows 95..99 ----
    {
        #pragma unroll
        for (int j = 0; j < TREM; ++j) {
            float ht = __ldg(h + (size_t)(NTILE * TILE - 1 + j) * BATCH_C
                             + block_b0 + tid);
            float xA = fmaf(A0, x, fmaf(A1, y, A4));
            float yA = fmaf(A2, x, fmaf(A3, y, A5));
            float xB = fmaf(B0, x, fmaf(B1, y, B4));
            float yB = fmaf(B2, x, fmaf(B3, y, B5));
            bool m = ht > p;
            x = m ? xB : xA;
            y = m ? yB : yA;
            so[j][tid] = make_float2(x, y);
        }
        __syncwarp();
        if (ttf < TREM) {
            float2* obase = out + (size_t)(block_b0 + wcol) * STRIDE
                          + NTILE * TILE + ttf;
            #pragma unroll
            for (int k = 0; k < 16; ++k)
                obase[(size_t)(2 * k) * STRIDE] = so[ttf][wcol + 2 * k];
        }
    }
}

// ---- generic fallback (any shape) ----
__global__ void ifs_generic(const float* __restrict__ coef,
                            const float* __restrict__ h,
                            float2* __restrict__ out,
                            int batch, int iters)
{
    int b = blockIdx.x * blockDim.x + threadIdx.x;
    if (b >= batch) return;
    const float4* c4 = reinterpret_cast<const float4*>(coef + (size_t)b * 12);
    float4 ca = c4[0], cb = c4[1], cc = c4[2];
    float A0=ca.x, A1=ca.y, A2=ca.z, A3=ca.w, A4=cb.x, A5=cb.y;
    float B0=cb.z, B1=cb.w, B2=cc.x, B3=cc.y, B4=cc.z, B5=cc.w;
    float j0 = fabsf(A0*A3 - A1*A2);
    float j1 = fabsf(B0*B3 - B1*B2);
    float p = j0 / (j0 + j1);
    float x = 0.05f, y = 0.05f;
    float2* o = out + (size_t)b * (iters + 1);
    o[0] = make_float2(x, y);
    for (int t = 0; t < iters; ++t) {
        float ht = __ldg(h + (size_t)t * batch + b);
        bool m = ht > p;
        float xn = fmaf(m?B0:A0, x, fmaf(m?B1:A1, y, m?B4:A4));
        float yn = fmaf(m?B2:A2, x, fmaf(m?B3:A3, y, m?B5:A5));
        x = xn; y = yn;
        o[t + 1] = make_float2(x, y);
    }
}

extern "C" void kernel_launch(void* const* d_in, const int* in_sizes, int n_in,
                              void* d_out, int out_size) {
    const float* coef = (const float*)d_in[0];
    const float* h    = (const float*)d_in[1];
    float2* out       = (float2*)d_out;

    int batch = in_sizes[0] / 12;
    int iters = in_sizes[1] / batch;

    if (batch == 200000 && iters == 100) {
        int blocks = (batch + BLOCK - 1) / BLOCK;
        ifs_spec<200000, 100><<<blocks, BLOCK>>>(coef, h, out);
    } else {
        int blocks = (batch + 255) / 256;
        ifs_generic<<<blocks, 256>>>(coef, h, out, batch, iters);
    }
}